// round 9
// baseline (speedup 1.0000x reference)
#include <cuda_runtime.h>
#include <cuda_fp16.h>
#include <math.h>
#include <stdint.h>

#define SZ 65535
#define THREADS 256
#define GRID 512

// ---- weight fragment image offsets (uint4 units) ----
#define ENC_F   0        // 8 n2 x 16 kt x 32
#define WIHR_F  4096     // 8 n2 x 8 kt x 32
#define WIHZ_F  6144
#define WIHN_F  8192
#define WHHR_F  10240
#define WHHZ_F  12288
#define WHHN_F  14336
#define VW_F    16384    // 4 n2 x 8 kt x 32
#define DEC_F   17408    // 1 n2 x 12 kt x 32
#define FRAG_TOTAL 17792

__device__ __align__(16) uint4 g_bh[FRAG_TOTAL];   // fp16 weight fragments

// ---- SMEM (bytes) — deliberately small: leaves ~91KB L1D with 2 CTAs/SM ----
#define OFF_X    0        // 32KB: obs staging (enc, 2x16KB slots) -> x -> h_out
#define OFF_H    32768    // 32KB: h (2 K blocks); block0 later = v
#define OFF_BR   65536
#define OFF_BZ   66048
#define OFF_BIN  66560
#define OFF_BHN  67072
#define OFF_ENCB 67584
#define OFF_VB   68096
#define OFF_DECB 68352
#define SMEM_TOTAL 68608

#define SWZ(o) ((o) ^ (((o) >> 3) & 0x70))

__device__ __forceinline__ uint32_t smem_u32(const void* p) {
    uint32_t a;
    asm("{ .reg .u64 t; cvta.to.shared.u64 t, %1; cvt.u32.u64 %0, t; }" : "=r"(a) : "l"(p));
    return a;
}

__device__ __forceinline__ void ldm4(uint32_t r[4], uint32_t a) {
    asm volatile("ldmatrix.sync.aligned.m8n8.x4.shared.b16 {%0,%1,%2,%3}, [%4];"
        : "=r"(r[0]), "=r"(r[1]), "=r"(r[2]), "=r"(r[3]) : "r"(a));
}

__device__ __forceinline__ void mma_f16(float c[4], const uint32_t a[4], uint32_t b0, uint32_t b1) {
    asm volatile("mma.sync.aligned.m16n8k16.row.col.f32.f16.f16.f32 "
        "{%0,%1,%2,%3}, {%4,%5,%6,%7}, {%8,%9}, {%0,%1,%2,%3};"
        : "+f"(c[0]), "+f"(c[1]), "+f"(c[2]), "+f"(c[3])
        : "r"(a[0]), "r"(a[1]), "r"(a[2]), "r"(a[3]), "r"(b0), "r"(b1));
}

__device__ __forceinline__ uint32_t packh2(float a, float b) {
    __half2 h = __floats2half2_rn(a, b);
    return *(uint32_t*)&h;
}
__device__ __forceinline__ float h_lo(uint32_t v) {
    return __half2float(__ushort_as_half((unsigned short)(v & 0xFFFF)));
}
__device__ __forceinline__ float h_hi(uint32_t v) {
    return __half2float(__ushort_as_half((unsigned short)(v >> 16)));
}

__device__ __forceinline__ float sigm(float x) { return 1.f / (1.f + __expf(-x)); }

__device__ __forceinline__ void store_pair(char* region, int row, int col, float a, float b) {
    uint32_t off = (uint32_t)((col >> 6) * 16384) + SWZ((uint32_t)(row * 128 + (col & 63) * 2));
    *(uint32_t*)(region + off) = packh2(a, b);
}

// [128 rows x 64 cols] fp32 gmem tile -> fp16 swizzled plane (direct)
__device__ void conv_tile(const float* __restrict__ g, int stride, int col0, int row0g,
                          char* dst, int tid) {
#pragma unroll
    for (int i = 0; i < 4; i++) {
        int t = tid + i * 256;
        int r = t >> 3, gi = t & 7;
        int gr = row0g + r;
        uint4 P;
        if (gr < SZ) {
            float4 a = *(const float4*)(g + (size_t)gr * stride + col0 + gi * 8);
            float4 b = *(const float4*)(g + (size_t)gr * stride + col0 + gi * 8 + 4);
            P.x = packh2(a.x, a.y); P.y = packh2(a.z, a.w);
            P.z = packh2(b.x, b.y); P.w = packh2(b.z, b.w);
        } else {
            P.x = P.y = P.z = P.w = 0u;
        }
        *(uint4*)(dst + SWZ((uint32_t)(r * 128 + gi * 16))) = P;
    }
}

// double-buffer halves: load+pack into regs / store regs to smem
__device__ __forceinline__ void conv_load_pack(const float* __restrict__ g, int stride, int col0,
                                               int row0g, uint32_t st[16], int tid) {
#pragma unroll
    for (int i = 0; i < 4; i++) {
        int t = tid + i * 256;
        int r = t >> 3, gi = t & 7;
        int gr = row0g + r;
        if (gr < SZ) {
            float4 a = *(const float4*)(g + (size_t)gr * stride + col0 + gi * 8);
            float4 b = *(const float4*)(g + (size_t)gr * stride + col0 + gi * 8 + 4);
            st[i * 4 + 0] = packh2(a.x, a.y); st[i * 4 + 1] = packh2(a.z, a.w);
            st[i * 4 + 2] = packh2(b.x, b.y); st[i * 4 + 3] = packh2(b.z, b.w);
        } else {
            st[i * 4 + 0] = st[i * 4 + 1] = st[i * 4 + 2] = st[i * 4 + 3] = 0u;
        }
    }
}
__device__ __forceinline__ void conv_store16(char* dst, const uint32_t st[16], int tid) {
#pragma unroll
    for (int i = 0; i < 4; i++) {
        int t = tid + i * 256;
        int r = t >> 3, gi = t & 7;
        uint4 P = make_uint4(st[i * 4 + 0], st[i * 4 + 1], st[i * 4 + 2], st[i * 4 + 3]);
        *(uint4*)(dst + SWZ((uint32_t)(r * 128 + gi * 16))) = P;
    }
}

// ---------------- prep: pack weights as fp16 mma B-fragments ----------------
__global__ void prep_kernel(const float* __restrict__ enc_w, const float* __restrict__ w_ih,
                            const float* __restrict__ w_hh, const float* __restrict__ v_w,
                            const float* __restrict__ dec_w) {
    int idx = blockIdx.x * blockDim.x + threadIdx.x;
    if (idx >= FRAG_TOTAL) return;
    const float* W; int ldw, nmax, ktc, base;
    if (idx < 4096)       { W = enc_w; ldw = 256; nmax = 128; base = 0; ktc = 16; }
    else if (idx < 10240) { int g = (idx - 4096) / 2048; W = w_ih + (size_t)g * 128 * 128;
                            ldw = 128; nmax = 128; base = 4096 + g * 2048; ktc = 8; }
    else if (idx < 16384) { int g = (idx - 10240) / 2048; W = w_hh + (size_t)g * 128 * 128;
                            ldw = 128; nmax = 128; base = 10240 + g * 2048; ktc = 8; }
    else if (idx < 17408) { W = v_w; ldw = 128; nmax = 64; base = 16384; ktc = 8; }
    else                  { W = dec_w; ldw = 192; nmax = 10; base = 17408; ktc = 12; }

    int local = idx - base;
    int n2 = local / (ktc * 32);
    int rem = local - n2 * ktc * 32;
    int kt = rem >> 5, lane = rem & 31;
    int n = n2 * 16 + (lane >> 2);
    int k = kt * 16 + (lane & 3) * 2;

    float w[8];
#pragma unroll
    for (int dn = 0; dn < 2; dn++)
#pragma unroll
        for (int dk = 0; dk < 2; dk++)
#pragma unroll
            for (int e = 0; e < 2; e++) {
                int nn = n + dn * 8, kk = k + dk * 8 + e;
                w[(dn + dk * 2) * 2 + e] = (nn < nmax) ? W[(size_t)nn * ldw + kk] : 0.f;
            }
    uint4 H;
    H.x = packh2(w[0], w[1]);
    H.y = packh2(w[2], w[3]);
    H.z = packh2(w[4], w[5]);
    H.w = packh2(w[6], w[7]);
    g_bh[idx] = H;
}

// n16-pair mma group: 2 mmas
__device__ __forceinline__ void mma1(float cE[4], float cO[4], const uint32_t a[4], uint4 Bh) {
    mma_f16(cE, a, Bh.x, Bh.z);
    mma_f16(cO, a, Bh.y, Bh.w);
}

// precompute 8 swizzled ldmatrix addresses for one A source
__device__ __forceinline__ void make_addrs(uint32_t areg, int arow, int kkp, uint32_t ad[8]) {
#pragma unroll
    for (int kt = 0; kt < 8; kt++) {
        int kk = kt * 16 + kkp;
        ad[kt] = areg + (uint32_t)((kk >> 6) * 16384) + SWZ((uint32_t)(arow * 128 + (kk & 63) * 2));
    }
}

// one A-source (ad[]+off) feeding ONE gate accumulator
__device__ __forceinline__ void gru_pass1(float (&A0)[8][4], const uint32_t ad[8], uint32_t off,
                                          int wn, int lane, int fb0) {
#pragma unroll
    for (int kt = 0; kt < 8; kt++) {
        uint4 B0[4];
#pragma unroll
        for (int l = 0; l < 4; l++) B0[l] = g_bh[fb0 + ((wn * 4 + l) * 8 + kt) * 32 + lane];
        uint32_t a[4];
        ldm4(a, ad[kt] + off);
#pragma unroll
        for (int l = 0; l < 4; l++) mma1(A0[2 * l], A0[2 * l + 1], a, B0[l]);
    }
}

#define ZERO84(a) { _Pragma("unroll") for (int _i = 0; _i < 8; _i++) _Pragma("unroll") for (int _j = 0; _j < 4; _j++) (a)[_i][_j] = 0.f; }

__global__ void __launch_bounds__(THREADS, 2)
ac_mma_kernel(const float* __restrict__ obs, const float* __restrict__ hid,
              const float* __restrict__ enc_b, const float* __restrict__ b_ih,
              const float* __restrict__ b_hh, const float* __restrict__ v_b,
              const float* __restrict__ dec_b,
              float* __restrict__ out, float* __restrict__ hout_g) {
    extern __shared__ char sm[];
    const uint32_t sbase = smem_u32(sm);
    const int tid = threadIdx.x, lane = tid & 31, wid = tid >> 5;
    const int wm = wid & 3, wn = wid >> 2;
    const int row0 = blockIdx.x * 128;

    float* s_br   = (float*)(sm + OFF_BR);
    float* s_bz   = (float*)(sm + OFF_BZ);
    float* s_bin  = (float*)(sm + OFF_BIN);
    float* s_bhn  = (float*)(sm + OFF_BHN);
    float* s_encb = (float*)(sm + OFF_ENCB);
    float* s_vb   = (float*)(sm + OFF_VB);
    float* s_decb = (float*)(sm + OFF_DECB);

    if (tid < 128) {
        s_br[tid]   = b_ih[tid] + b_hh[tid];
        s_bz[tid]   = b_ih[128 + tid] + b_hh[128 + tid];
        s_bin[tid]  = b_ih[256 + tid];
        s_bhn[tid]  = b_hh[256 + tid];
        s_encb[tid] = enc_b[tid];
    }
    if (tid < 64) s_vb[tid]   = v_b[tid];
    if (tid < 16) s_decb[tid] = (tid < 10) ? dec_b[tid] : 0.f;

    // h -> fp16 plane (2 K blocks)
    conv_tile(hid, 128, 0,  row0, sm + OFF_H,         tid);
    conv_tile(hid, 128, 64, row0, sm + OFF_H + 16384, tid);

    const uint32_t xreg = sbase + OFF_X;
    const uint32_t hreg = sbase + OFF_H;
    const int kkp = (lane >> 4) << 3;

    // ======== enc GEMM: obs @ enc_w^T (K=256); obs staged inside X region ========
    {
        float acc[2][8][4];
#pragma unroll
        for (int mi = 0; mi < 2; mi++) ZERO84(acc[mi]);

        conv_tile(obs, 256, 0, row0, sm + OFF_X, tid);   // chunk 0 -> slot 0
        __syncthreads();

        uint32_t st[16];
        for (int kb = 0; kb < 4; kb++) {
            const uint32_t slotr = xreg + (uint32_t)((kb & 1) * 16384);
            if (kb < 3) conv_load_pack(obs, 256, (kb + 1) * 64, row0, st, tid);
#pragma unroll
            for (int kt4 = 0; kt4 < 4; kt4++) {
                int ktg = kb * 4 + kt4;
                uint4 B[4];
#pragma unroll
                for (int l = 0; l < 4; l++)
                    B[l] = g_bh[ENC_F + ((wn * 4 + l) * 16 + ktg) * 32 + lane];
                uint32_t a[2][4];
#pragma unroll
                for (int mi = 0; mi < 2; mi++) {
                    int arow = wm * 32 + mi * 16 + (lane & 15);
                    ldm4(a[mi], slotr + SWZ((uint32_t)(arow * 128 + (kt4 * 16 + kkp) * 2)));
                }
#pragma unroll
                for (int l = 0; l < 4; l++)
#pragma unroll
                    for (int mi = 0; mi < 2; mi++)
                        mma1(acc[mi][2 * l], acc[mi][2 * l + 1], a[mi], B[l]);
            }
            if (kb < 3) conv_store16(sm + OFF_X + (((kb + 1) & 1) * 16384), st, tid);
            __syncthreads();
        }

        // x = relu(acc + b) -> s_x (obs staging dead; synced above)
        int rb = wm * 32 + (lane >> 2);
#pragma unroll
        for (int mi = 0; mi < 2; mi++)
#pragma unroll
            for (int ni = 0; ni < 8; ni++) {
                int col = wn * 64 + ni * 8 + (lane & 3) * 2;
                float b0 = s_encb[col], b1 = s_encb[col + 1];
#pragma unroll
                for (int rp = 0; rp < 2; rp++) {
                    int row = rb + mi * 16 + rp * 8;
                    store_pair(sm + OFF_X, row, col,
                               fmaxf(acc[mi][ni][rp * 2 + 0] + b0, 0.f),
                               fmaxf(acc[mi][ni][rp * 2 + 1] + b1, 0.f));
                }
            }
    }
    __syncthreads();

    // ======== GRU: two 64-row halves, gate order r -> n -> z, state in regs ========
    for (int hp = 0; hp < 2; hp++) {
        int mrow = hp * 64 + wm * 16;
        uint32_t ax[8];
        make_addrs(xreg, mrow + (lane & 15), kkp, ax);   // h source = ax + 32768

        // ---- pass r ----
        uint32_t sr[16];
        {
            float rg[8][4];
            ZERO84(rg);
            gru_pass1(rg, ax, 0u,     wn, lane, WIHR_F);
            gru_pass1(rg, ax, 32768u, wn, lane, WHHR_F);
#pragma unroll
            for (int ni = 0; ni < 8; ni++) {
                int col = wn * 64 + ni * 8 + (lane & 3) * 2;
                float br0 = s_br[col], br1 = s_br[col + 1];
#pragma unroll
                for (int rp = 0; rp < 2; rp++)
                    sr[ni * 2 + rp] = packh2(sigm(rg[ni][rp * 2 + 0] + br0),
                                             sigm(rg[ni][rp * 2 + 1] + br1));
            }
        }

        // ---- pass n: nt = tanh(an + bin + r*(hn + bhn)) ----
        uint32_t nt[16];
        {
            float an[8][4], hn[8][4];
            ZERO84(an); ZERO84(hn);
            gru_pass1(an, ax, 0u,     wn, lane, WIHN_F);
            gru_pass1(hn, ax, 32768u, wn, lane, WHHN_F);
#pragma unroll
            for (int ni = 0; ni < 8; ni++) {
                int col = wn * 64 + ni * 8 + (lane & 3) * 2;
                float bi0 = s_bin[col], bi1 = s_bin[col + 1];
                float bh0 = s_bhn[col], bh1 = s_bhn[col + 1];
#pragma unroll
                for (int rp = 0; rp < 2; rp++) {
                    float r0 = h_lo(sr[ni * 2 + rp]), r1 = h_hi(sr[ni * 2 + rp]);
                    nt[ni * 2 + rp] = packh2(
                        tanhf(an[ni][rp * 2 + 0] + bi0 + r0 * (hn[ni][rp * 2 + 0] + bh0)),
                        tanhf(an[ni][rp * 2 + 1] + bi1 + r1 * (hn[ni][rp * 2 + 1] + bh1)));
                }
            }
        }

        // ---- pass z + epilogue ----
        {
            float zg[8][4];
            ZERO84(zg);
            gru_pass1(zg, ax, 0u,     wn, lane, WIHZ_F);
            gru_pass1(zg, ax, 32768u, wn, lane, WHHZ_F);
            __syncthreads();   // all s_x/s_h reads of this half done before overwriting s_x

            int rb = mrow + (lane >> 2);
#pragma unroll
            for (int ni = 0; ni < 8; ni++) {
                int col = wn * 64 + ni * 8 + (lane & 3) * 2;
                float bz0 = s_bz[col], bz1 = s_bz[col + 1];
#pragma unroll
                for (int rp = 0; rp < 2; rp++) {
                    int row = rb + rp * 8;
                    int grow = row0 + row;
                    float h0 = 0.f, h1 = 0.f;
                    if (grow < SZ) {
                        float2 t = *(const float2*)(hid + (size_t)grow * 128 + col);
                        h0 = t.x; h1 = t.y;
                    }
                    float z0 = sigm(zg[ni][rp * 2 + 0] + bz0);
                    float z1 = sigm(zg[ni][rp * 2 + 1] + bz1);
                    float n0 = h_lo(nt[ni * 2 + rp]), n1 = h_hi(nt[ni * 2 + rp]);
                    float o0 = (1.f - z0) * n0 + z0 * h0;
                    float o1 = (1.f - z1) * n1 + z1 * h1;
                    if (grow < SZ)
                        *(float2*)(hout_g + (size_t)grow * 128 + col) = make_float2(o0, o1);
                    store_pair(sm + OFF_X, row, col, o0, o1);
                }
            }
        }
        __syncthreads();
    }

    // ======== v GEMM: 128x64, A = h_out (s_x), K=128 ========
    {
        float vc[2][4][4];
#pragma unroll
        for (int mi = 0; mi < 2; mi++)
#pragma unroll
            for (int ni = 0; ni < 4; ni++)
#pragma unroll
                for (int j = 0; j < 4; j++) vc[mi][ni][j] = 0.f;
#pragma unroll
        for (int kt = 0; kt < 8; kt++) {
            int kk = kt * 16 + kkp;
            uint4 B[2];
#pragma unroll
            for (int l = 0; l < 2; l++)
                B[l] = g_bh[VW_F + ((wn * 2 + l) * 8 + kt) * 32 + lane];
            uint32_t a[2][4];
#pragma unroll
            for (int mi = 0; mi < 2; mi++) {
                int arow = wm * 32 + mi * 16 + (lane & 15);
                ldm4(a[mi], xreg + (uint32_t)((kk >> 6) * 16384) + SWZ((uint32_t)(arow * 128 + (kk & 63) * 2)));
            }
#pragma unroll
            for (int l = 0; l < 2; l++)
#pragma unroll
                for (int mi = 0; mi < 2; mi++)
                    mma1(vc[mi][2 * l], vc[mi][2 * l + 1], a[mi], B[l]);
        }
        // v -> s_h block 0
#pragma unroll
        for (int mi = 0; mi < 2; mi++)
#pragma unroll
            for (int ni = 0; ni < 4; ni++) {
                int col = wn * 32 + ni * 8 + (lane & 3) * 2;
                float b0 = s_vb[col], b1 = s_vb[col + 1];
#pragma unroll
                for (int rp = 0; rp < 2; rp++) {
                    int row = wm * 32 + mi * 16 + (lane >> 2) + rp * 8;
                    store_pair(sm + OFF_H, row, col,
                               fmaxf(vc[mi][ni][rp * 2 + 0] + b0, 0.f),
                               fmaxf(vc[mi][ni][rp * 2 + 1] + b1, 0.f));
                }
            }
    }
    __syncthreads();

    // ======== dec GEMM: [h_out | v] @ dec_w^T, K=192, N=16 ========
    {
        float dc[2][4];
#pragma unroll
        for (int mi = 0; mi < 2; mi++)
#pragma unroll
            for (int j = 0; j < 4; j++) dc[mi][j] = 0.f;
#pragma unroll
        for (int kt = 0; kt < 12; kt++) {
            uint32_t areg2 = (kt < 8) ? xreg : hreg;
            int kk = ((kt < 8) ? kt : (kt - 8)) * 16 + kkp;
            uint4 Bh = g_bh[DEC_F + kt * 32 + lane];
            uint32_t a[2][4];
#pragma unroll
            for (int mi = 0; mi < 2; mi++) {
                int arow = wm * 32 + mi * 16 + (lane & 15);
                ldm4(a[mi], areg2 + (uint32_t)((kk >> 6) * 16384) + SWZ((uint32_t)(arow * 128 + (kk & 63) * 2)));
            }
            uint32_t b0h = wn ? Bh.y : Bh.x, b1h = wn ? Bh.w : Bh.z;
#pragma unroll
            for (int mi = 0; mi < 2; mi++)
                mma_f16(dc[mi], a[mi], b0h, b1h);
        }
        int col = wn * 8 + (lane & 3) * 2;
        float b0 = s_decb[col], b1 = s_decb[col + 1];
#pragma unroll
        for (int mi = 0; mi < 2; mi++)
#pragma unroll
            for (int rp = 0; rp < 2; rp++) {
                int row = wm * 32 + mi * 16 + (lane >> 2) + rp * 8;
                int grow = row0 + row;
                if (grow < SZ) {
                    float o0 = dc[mi][rp * 2 + 0] + b0;
                    float o1 = dc[mi][rp * 2 + 1] + b1;
                    if (col < 10)     out[(size_t)grow * 10 + col] = o0;
                    if (col + 1 < 10) out[(size_t)grow * 10 + col + 1] = o1;
                }
            }
    }
}

extern "C" void kernel_launch(void* const* d_in, const int* in_sizes, int n_in,
                              void* d_out, int out_size) {
    const float* obs   = (const float*)d_in[0];
    const float* hid   = (const float*)d_in[1];
    const float* enc_w = (const float*)d_in[2];
    const float* enc_b = (const float*)d_in[3];
    const float* w_ih  = (const float*)d_in[4];
    const float* w_hh  = (const float*)d_in[5];
    const float* b_ih  = (const float*)d_in[6];
    const float* b_hh  = (const float*)d_in[7];
    const float* v_w   = (const float*)d_in[20];
    const float* v_b   = (const float*)d_in[21];
    const float* dec_w = (const float*)d_in[22];
    const float* dec_b = (const float*)d_in[23];

    float* out  = (float*)d_out;
    float* hout = out + (size_t)SZ * 10;

    prep_kernel<<<(FRAG_TOTAL + 255) / 256, 256>>>(enc_w, w_ih, w_hh, v_w, dec_w);

    cudaFuncSetAttribute(ac_mma_kernel, cudaFuncAttributeMaxDynamicSharedMemorySize, SMEM_TOTAL);
    ac_mma_kernel<<<GRID, THREADS, SMEM_TOTAL>>>(obs, hid, enc_b, b_ih, b_hh, v_b, dec_b, out, hout);
}